// round 2
// baseline (speedup 1.0000x reference)
#include <cuda_runtime.h>

#define CH   4194304      // 256*256*64
#define SXY  16384        // 256*64 (x stride)
#define EPSF 1e-10f

__device__ double g_acc[3];   // [0]=loss_b sum, [1]=parallel sum, [2]=div sum

__global__ void k_zero() {
    if (threadIdx.x < 3) g_acc[threadIdx.x] = 0.0;
}

__global__ void k_final(float* out) {
    const double N1 = 8388608.0;   // 2*256*256*64
    const double N2 = 8193150.0;   // 2*255*255*63
    double lb = g_acc[0] / N1;
    double lp = g_acc[1] / N1;
    double ld = g_acc[2] / N2;
    double dx2 = 0.1 * 0.1;
    out[0] = (float)(1000.0 * lb + 1000.0 * lp);
    out[1] = (float)(100.0 * ld / dx2 / dx2);
}

__global__ __launch_bounds__(256)
void k_main(const float* __restrict__ O, const float* __restrict__ T) {
    const int tx = threadIdx.x;          // 0..15 -> k chunk (k0 = 4*tx)
    const int ty = threadIdx.y;          // 0..15 -> y within group
    const int bid = blockIdx.x;          // 8192 blocks: (b, x, ygroup)
    const int y  = ((bid & 15) << 4) + ty;
    const int x  = (bid >> 4) & 255;
    const int b  = bid >> 12;
    const int k0 = tx << 2;
    const int sp = (x * 256 + y) * 64 + k0;
    const int ob = b * 3 * CH;           // outputs batch base
    const int tb = b * 4 * CH;           // targets batch base

    const float4* O4 = (const float4*)O;
    const float4* T4 = (const float4*)T;

    // ---- pointwise channel loads (also serve as (0,0,k0..k0+3) stencil corners) ----
    float4 pbx = O4[(ob           + sp) >> 2];
    float4 pby = O4[(ob + CH      + sp) >> 2];
    float4 pbz = O4[(ob + 2 * CH  + sp) >> 2];
    float4 qbx = T4[(tb           + sp) >> 2];
    float4 qby = T4[(tb + CH      + sp) >> 2];
    float4 qbz = T4[(tb + 2 * CH  + sp) >> 2];

    float accb = 0.f, accp = 0.f, accd = 0.f;

#define PW(px, py, pz, qx, qy, qz) {                                   \
    float qx2 = (qx)*(qx), qy2 = (qy)*(qy), qz2 = (qz)*(qz);           \
    float v1 = (px)*(px) + (py)*(py) - qx2 - qy2;                      \
    accb += __fdividef(v1 * v1, qx2 + qy2 + EPSF);                     \
    float dz = (pz) - (qz); float dz2 = dz * dz;                       \
    accb += __fdividef(dz2 * dz2, qz2 + EPSF);                         \
    float cr = (px)*(qy) - (py)*(qx);                                  \
    accp += __fdividef(cr * cr, qx2 + qy2 + qz2 + EPSF); }

    PW(pbx.x, pby.x, pbz.x, qbx.x, qby.x, qbz.x);
    PW(pbx.y, pby.y, pbz.y, qbx.y, qby.y, qbz.y);
    PW(pbx.z, pby.z, pbz.z, qbx.z, qby.z, qbz.z);
    PW(pbx.w, pby.w, pbz.w, qbx.w, qby.w, qbz.w);
#undef PW

    // ---- divergence stencil over cells (x<255, y<255, k<63) ----
    // Load the 3 spatial neighbor rows unconditionally (always in-bounds for
    // the load when x<255 && y<255; guarded). The k0+4 tail element comes from
    // lane tx+1's .x component via shfl (lane+1 in the same warp half-row).
    const bool live = (x < 255) && (y < 255);

    float4 fx10, fx01, fx11, fy10, fy01, fy11, fz10, fz01, fz11;
    float4 fw00, fw10, fw01, fw11;
    if (live) {
        const int s10 = sp + SXY;      // x+1
        const int s01 = sp + 64;       // y+1
        const int s11 = s10 + 64;      // x+1, y+1
        const int cz  = tb + 3 * CH;   // targets channel 3 (z)
        fx10 = O4[(ob          + s10) >> 2];
        fx01 = O4[(ob          + s01) >> 2];
        fx11 = O4[(ob          + s11) >> 2];
        fy10 = O4[(ob + CH     + s10) >> 2];
        fy01 = O4[(ob + CH     + s01) >> 2];
        fy11 = O4[(ob + CH     + s11) >> 2];
        fz10 = O4[(ob + 2*CH   + s10) >> 2];
        fz01 = O4[(ob + 2*CH   + s01) >> 2];
        fz11 = O4[(ob + 2*CH   + s11) >> 2];
        fw00 = T4[(cz          + sp ) >> 2];
        fw10 = T4[(cz          + s10) >> 2];
        fw01 = T4[(cz          + s01) >> 2];
        fw11 = T4[(cz          + s11) >> 2];
    } else {
        fx10 = fx01 = fx11 = fy10 = fy01 = fy11 = fz10 = fz01 = fz11 =
        fw00 = fw10 = fw01 = fw11 = make_float4(0.f, 0.f, 0.f, 0.f);
    }

    // k0+4 tail via shfl from lane+1 (.x of each neighbor's loads). All lanes
    // participate (full mask); tx==15 result is unused (k0+3 == 62 is last cell).
    const unsigned FULL = 0xffffffffu;
    float tBX00 = __shfl_down_sync(FULL, pbx.x,  1);
    float tBX10 = __shfl_down_sync(FULL, fx10.x, 1);
    float tBX01 = __shfl_down_sync(FULL, fx01.x, 1);
    float tBX11 = __shfl_down_sync(FULL, fx11.x, 1);
    float tBY00 = __shfl_down_sync(FULL, pby.x,  1);
    float tBY10 = __shfl_down_sync(FULL, fy10.x, 1);
    float tBY01 = __shfl_down_sync(FULL, fy01.x, 1);
    float tBY11 = __shfl_down_sync(FULL, fy11.x, 1);
    float tBZ00 = __shfl_down_sync(FULL, pbz.x,  1);
    float tBZ10 = __shfl_down_sync(FULL, fz10.x, 1);
    float tBZ01 = __shfl_down_sync(FULL, fz01.x, 1);
    float tBZ11 = __shfl_down_sync(FULL, fz11.x, 1);
    float tZZ00 = __shfl_down_sync(FULL, fw00.x, 1);
    float tZZ10 = __shfl_down_sync(FULL, fw10.x, 1);
    float tZZ01 = __shfl_down_sync(FULL, fw01.x, 1);
    float tZZ11 = __shfl_down_sync(FULL, fw11.x, 1);

    if (live) {
        float BX00[5] = {pbx.x, pbx.y, pbx.z, pbx.w, tBX00};
        float BX10[5] = {fx10.x, fx10.y, fx10.z, fx10.w, tBX10};
        float BX01[5] = {fx01.x, fx01.y, fx01.z, fx01.w, tBX01};
        float BX11[5] = {fx11.x, fx11.y, fx11.z, fx11.w, tBX11};
        float BY00[5] = {pby.x, pby.y, pby.z, pby.w, tBY00};
        float BY10[5] = {fy10.x, fy10.y, fy10.z, fy10.w, tBY10};
        float BY01[5] = {fy01.x, fy01.y, fy01.z, fy01.w, tBY01};
        float BY11[5] = {fy11.x, fy11.y, fy11.z, fy11.w, tBY11};
        float BZ00[5] = {pbz.x, pbz.y, pbz.z, pbz.w, tBZ00};
        float BZ10[5] = {fz10.x, fz10.y, fz10.z, fz10.w, tBZ10};
        float BZ01[5] = {fz01.x, fz01.y, fz01.z, fz01.w, tBZ01};
        float BZ11[5] = {fz11.x, fz11.y, fz11.z, fz11.w, tBZ11};
        float ZZ00[5] = {fw00.x, fw00.y, fw00.z, fw00.w, tZZ00};
        float ZZ10[5] = {fw10.x, fw10.y, fw10.z, fw10.w, tZZ10};
        float ZZ01[5] = {fw01.x, fw01.y, fw01.z, fw01.w, tZZ01};
        float ZZ11[5] = {fw11.x, fw11.y, fw11.z, fw11.w, tZZ11};

        const float DXf = 0.1f, DYf = 0.1f;
        const float SIXTH = 1.f / 6.f;

#pragma unroll
        for (int j = 0; j < 4; j++) {
            if (k0 + j < 63) {
                float bx000 = BX00[j], bx001 = BX00[j+1];
                float bx100 = BX10[j], bx101 = BX10[j+1];
                float bx010 = BX01[j], bx011 = BX01[j+1];
                float bx110 = BX11[j], bx111 = BX11[j+1];
                float by000 = BY00[j], by001 = BY00[j+1];
                float by100 = BY10[j], by101 = BY10[j+1];
                float by010 = BY01[j], by011 = BY01[j+1];
                float by110 = BY11[j], by111 = BY11[j+1];
                float bz000 = BZ00[j], bz001 = BZ00[j+1];
                float bz100 = BZ10[j], bz101 = BZ10[j+1];
                float bz010 = BZ01[j], bz011 = BZ01[j+1];
                float bz110 = BZ11[j], bz111 = BZ11[j+1];
                float z000  = ZZ00[j], z001  = ZZ00[j+1];
                float z100  = ZZ10[j], z101  = ZZ10[j+1];
                float z010  = ZZ01[j], z011  = ZZ01[j+1];
                float z110  = ZZ11[j], z111  = ZZ11[j+1];

                float num =
                    0.25f*(bx100+bx110+bx101+bx111) * DYf * 0.5f*(z101 - z100 + z111 - z110)
                  - 0.25f*(bx000+bx010+bx001+bx011) * DYf * 0.5f*(z001 - z000 + z011 - z010)
                  + 0.25f*(by010+by110+by011+by111) * DXf * 0.5f*(z011 - z010 + z111 - z110)
                  - 0.25f*(by000+by100+by001+by101) * DXf * 0.5f*(z001 - z000 + z101 - z100)
                  + 0.25f*(bz001+bz011+bz101+bz111) * DXf * DYf
                  - 0.25f*(bz000+bz010+bz100+bz110) * DXf * DYf
                  + (bx001+bx101+bx111) * DYf * (z001 - z101) * SIXTH
                  + (bx011+bx111+bx101) * DYf * (z011 - z111) * SIXTH
                  + (by101+by111+by011) * DXf * (z101 - z111) * SIXTH
                  + (by001+by011+by111) * DXf * (z001 - z011) * SIXTH
                  - (bx000+bx100+bx110) * DYf * (z000 - z100) * SIXTH
                  - (bx010+bx110+bx100) * DYf * (z010 - z110) * SIXTH
                  - (by100+by110+by010) * DXf * (z100 - z110) * SIXTH
                  - (by000+by010+by110) * DXf * (z000 - z010) * SIXTH;

                float bxc = 0.125f*(bx000+bx100+bx010+bx110+bx001+bx101+bx011+bx111);
                float byc = 0.125f*(by000+by100+by010+by110+by001+by101+by011+by111);
                float bzc = 0.125f*(bz000+bz100+bz010+bz110+bz001+bz101+bz011+bz111);
                float den = bxc*bxc + byc*byc + bzc*bzc + EPSF;
                accd += __fdividef(num * num, den);
            }
        }
    }

    // ---- reduction: warp shfl (double) -> smem -> 3 atomics per block ----
    double db = (double)accb, dp = (double)accp, dd = (double)accd;
#pragma unroll
    for (int o = 16; o > 0; o >>= 1) {
        db += __shfl_xor_sync(0xffffffffu, db, o);
        dp += __shfl_xor_sync(0xffffffffu, dp, o);
        dd += __shfl_xor_sync(0xffffffffu, dd, o);
    }
    __shared__ double sb[8], sp_[8], sd[8];
    int lin = ty * 16 + tx;
    if ((lin & 31) == 0) {
        int w = lin >> 5;
        sb[w] = db; sp_[w] = dp; sd[w] = dd;
    }
    __syncthreads();
    if (lin == 0) {
        double a = 0.0, c = 0.0, d = 0.0;
#pragma unroll
        for (int w = 0; w < 8; w++) { a += sb[w]; c += sp_[w]; d += sd[w]; }
        atomicAdd(&g_acc[0], a);
        atomicAdd(&g_acc[1], c);
        atomicAdd(&g_acc[2], d);
    }
}

extern "C" void kernel_launch(void* const* d_in, const int* in_sizes, int n_in,
                              void* d_out, int out_size) {
    const float* O = (const float*)d_in[0];   // outputs (2,3,256,256,64)
    const float* T = (const float*)d_in[1];   // targets (2,4,256,256,64)
    k_zero<<<1, 32>>>();
    k_main<<<8192, dim3(16, 16)>>>(O, T);
    k_final<<<1, 1>>>((float*)d_out);
}